// round 8
// baseline (speedup 1.0000x reference)
#include <cuda_runtime.h>
#include <cstdint>

#define THREADS 128
#define DIMV 32
#define NHV 24
#define NP 12      // packed h-pairs per 24
#define KLV 31     // dim-1 stacked layers
#define BLOBK 2048 // floats per k in the packed blob

// packed-blob / shared weight-buffer offsets (floats) — W1 transposed to [j][h]
#define OW1 0      // 32*24 = 768
#define OW2 768    // 576
#define OW3 1344   // 576
#define OW4 1920   // 48
#define OB1 1968   // 24
#define OB2 1992   // 24
#define OB3 2016   // 24
#define OB4 2040   // 2
#define WTOT 2042

__device__ float g_blob[KLV * BLOBK];   // pre-transposed weights, 254KB

// ---- packed f32x2 helpers (sm_100+) ----
__device__ __forceinline__ void ffma2(uint64_t& c, uint64_t a, uint64_t b) {
    asm("fma.rn.f32x2 %0, %1, %2, %0;" : "+l"(c) : "l"(a), "l"(b));
}
__device__ __forceinline__ uint64_t add2(uint64_t a, uint64_t b) {
    uint64_t r; asm("add.rn.f32x2 %0, %1, %2;" : "=l"(r) : "l"(a), "l"(b)); return r;
}
__device__ __forceinline__ uint64_t pack2(float lo, float hi) {
    uint64_t r; asm("mov.b64 %0, {%1, %2};" : "=l"(r) : "f"(lo), "f"(hi)); return r;
}
__device__ __forceinline__ void unpack2(uint64_t v, float& lo, float& hi) {
    asm("mov.b64 {%0, %1}, %2;" : "=f"(lo), "=f"(hi) : "l"(v));
}
__device__ __forceinline__ uint64_t lrelu2(uint64_t v) {
    float lo, hi; unpack2(v, lo, hi);
    lo = fmaxf(lo, 0.2f * lo);
    hi = fmaxf(hi, 0.2f * hi);
    return pack2(lo, hi);
}
__device__ __forceinline__ float lrelu(float v) { return fmaxf(v, 0.2f * v); }

// ---- one-time weight prepack: blob[k][...] with W1 transposed to [j][h] ----
__global__ void prepack_kernel(const float* __restrict__ W1, const float* __restrict__ b1,
                               const float* __restrict__ W2, const float* __restrict__ b2,
                               const float* __restrict__ W3, const float* __restrict__ b3,
                               const float* __restrict__ W4, const float* __restrict__ b4)
{
    int idx = blockIdx.x * blockDim.x + threadIdx.x;
    if (idx >= KLV * BLOBK) return;
    int k = idx >> 11, f = idx & (BLOBK - 1);
    float v = 0.f;
    if (f < 768)       { int j = f / 24, h = f - j * 24; v = W1[k * 768 + h * 32 + j]; }
    else if (f < 1344) v = W2[k * 576 + (f - 768)];
    else if (f < 1920) v = W3[k * 576 + (f - 1344)];
    else if (f < 1968) v = W4[k * 48  + (f - 1920)];
    else if (f < 1992) v = b1[k * 24  + (f - 1968)];
    else if (f < 2016) v = b2[k * 24  + (f - 1992)];
    else if (f < 2040) v = b3[k * 24  + (f - 2016)];
    else if (f < WTOT) v = b4[k * 2   + (f - 2040)];
    g_blob[idx] = v;
}

__global__ void __launch_bounds__(THREADS, 2)
maf_kernel(const float* __restrict__ x, const float* __restrict__ p0,
           float* __restrict__ z, float* __restrict__ logdet)
{
    // xs: 2 rows x 32 floats per thread, XOR-swizzled (bank = elem ^ lane) => conflict-free
    __shared__ float xs[THREADS * 64];          // 32 KB
    __shared__ float wbuf[2][BLOBK];            // 16 KB, double-buffered weights

    const int tid = threadIdx.x;
    const int tx  = tid & 31;
    const int xb  = tid * 64;
    const size_t r0 = ((size_t)blockIdx.x * THREADS + tid) * 2;

    // ---- load both x rows into swizzled shared (thread-private) ----
    {
        const float4* xa = reinterpret_cast<const float4*>(x + r0 * DIMV);
        const float4* xc = reinterpret_cast<const float4*>(x + (r0 + 1) * DIMV);
        #pragma unroll
        for (int q = 0; q < 8; q++) {
            float4 v = xa[q];
            xs[xb + ((4 * q + 0) ^ tx)] = v.x;  xs[xb + ((4 * q + 1) ^ tx)] = v.y;
            xs[xb + ((4 * q + 2) ^ tx)] = v.z;  xs[xb + ((4 * q + 3) ^ tx)] = v.w;
            float4 w = xc[q];
            xs[xb + 32 + ((4 * q + 0) ^ tx)] = w.x;  xs[xb + 32 + ((4 * q + 1) ^ tx)] = w.y;
            xs[xb + 32 + ((4 * q + 2) ^ tx)] = w.z;  xs[xb + 32 + ((4 * q + 3) ^ tx)] = w.w;
        }
    }

    uint32_t wsm[2];
    wsm[0] = (uint32_t)__cvta_generic_to_shared(&wbuf[0][0]);
    wsm[1] = (uint32_t)__cvta_generic_to_shared(&wbuf[1][0]);

    // async weight fetch: 8192 B per k, 4 x 16B per thread
    auto cpw = [&](int k, int pbuf) {
        const char* src = reinterpret_cast<const char*>(g_blob + (size_t)k * BLOBK) + tid * 16;
        uint32_t dst = wsm[pbuf] + tid * 16;
        #pragma unroll
        for (int i = 0; i < 4; i++)
            asm volatile("cp.async.cg.shared.global [%0], [%1], 16;"
                         :: "r"(dst + i * 2048), "l"(src + i * 2048));
        asm volatile("cp.async.commit_group;");
    };

    // prologue: stage k=0
    cpw(0, 0);
    asm volatile("cp.async.wait_group 0;" ::: "memory");
    __syncthreads();

    float ldet0 = 0.f, ldet1 = 0.f;
    uint64_t A0[NP], A1[NP], B0[NP], B1[NP];
    int p = 0;

    for (int k = 0; k < KLV; k++) {
        if (k + 1 < KLV) cpw(k + 1, p ^ 1);    // prefetch overlaps full compute
        const float* wb = wbuf[p];

        // ---- layer 1: A[h] = lrelu( sum_{j<=k} W1T[j][h] * x[j] + b1[h] ) ----
        #pragma unroll
        for (int q = 0; q < NP; q++) {
            uint64_t bb = *reinterpret_cast<const uint64_t*>(&wb[OB1 + 2 * q]);
            A0[q] = bb; A1[q] = bb;
        }
        for (int j = 0; j <= k; j++) {
            int js = j ^ tx;
            float x0 = xs[xb + js], x1 = xs[xb + 32 + js];
            uint64_t xx0 = pack2(x0, x0), xx1 = pack2(x1, x1);
            const ulonglong2* w = reinterpret_cast<const ulonglong2*>(&wb[OW1 + j * NHV]);
            #pragma unroll
            for (int q = 0; q < 6; q++) {
                ulonglong2 wp = w[q];               // LDS.128 = 2 packed weight pairs
                ffma2(A0[2 * q + 0], wp.x, xx0);
                ffma2(A0[2 * q + 1], wp.y, xx0);
                ffma2(A1[2 * q + 0], wp.x, xx1);
                ffma2(A1[2 * q + 1], wp.y, xx1);
            }
        }
        #pragma unroll
        for (int q = 0; q < NP; q++) { A0[q] = lrelu2(A0[q]); A1[q] = lrelu2(A1[q]); }

        // ---- layer 2: dense 24x24 ----
        #pragma unroll
        for (int Hp = 0; Hp < NP; Hp++) {
            float o0e, o0o, o1e, o1o;
            #pragma unroll
            for (int e = 0; e < 2; e++) {
                int H = 2 * Hp + e;
                const ulonglong2* w = reinterpret_cast<const ulonglong2*>(&wb[OW2 + H * NHV]);
                uint64_t s0 = 0, t0 = 0, s1 = 0, t1 = 0;
                #pragma unroll
                for (int q = 0; q < 6; q++) {
                    ulonglong2 wp = w[q];
                    ffma2(s0, wp.x, A0[2 * q + 0]);
                    ffma2(t0, wp.y, A0[2 * q + 1]);
                    ffma2(s1, wp.x, A1[2 * q + 0]);
                    ffma2(t1, wp.y, A1[2 * q + 1]);
                }
                float bH = wb[OB2 + H];
                float a, b, c, d;
                unpack2(add2(s0, t0), a, b);
                unpack2(add2(s1, t1), c, d);
                float v0 = lrelu(a + b + bH);
                float v1 = lrelu(c + d + bH);
                if (e == 0) { o0e = v0; o1e = v1; } else { o0o = v0; o1o = v1; }
            }
            B0[Hp] = pack2(o0e, o0o);
            B1[Hp] = pack2(o1e, o1o);
        }

        // ---- layer 3: dense 24x24 ----
        #pragma unroll
        for (int Hp = 0; Hp < NP; Hp++) {
            float o0e, o0o, o1e, o1o;
            #pragma unroll
            for (int e = 0; e < 2; e++) {
                int H = 2 * Hp + e;
                const ulonglong2* w = reinterpret_cast<const ulonglong2*>(&wb[OW3 + H * NHV]);
                uint64_t s0 = 0, t0 = 0, s1 = 0, t1 = 0;
                #pragma unroll
                for (int q = 0; q < 6; q++) {
                    ulonglong2 wp = w[q];
                    ffma2(s0, wp.x, B0[2 * q + 0]);
                    ffma2(t0, wp.y, B0[2 * q + 1]);
                    ffma2(s1, wp.x, B1[2 * q + 0]);
                    ffma2(t1, wp.y, B1[2 * q + 1]);
                }
                float bH = wb[OB3 + H];
                float a, b, c, d;
                unpack2(add2(s0, t0), a, b);
                unpack2(add2(s1, t1), c, d);
                float v0 = lrelu(a + b + bH);
                float v1 = lrelu(c + d + bH);
                if (e == 0) { o0e = v0; o1e = v1; } else { o0o = v0; o1o = v1; }
            }
            A0[Hp] = pack2(o0e, o0o);
            A1[Hp] = pack2(o1e, o1o);
        }

        // ---- layer 4: (s, t) per row ----
        float sv0, tv0, sv1, tv1;
        #pragma unroll
        for (int o = 0; o < 2; o++) {
            const ulonglong2* w = reinterpret_cast<const ulonglong2*>(&wb[OW4 + o * NHV]);
            uint64_t s0 = 0, t0 = 0, s1 = 0, t1 = 0;
            #pragma unroll
            for (int q = 0; q < 6; q++) {
                ulonglong2 wp = w[q];
                ffma2(s0, wp.x, A0[2 * q + 0]);
                ffma2(t0, wp.y, A0[2 * q + 1]);
                ffma2(s1, wp.x, A1[2 * q + 0]);
                ffma2(t1, wp.y, A1[2 * q + 1]);
            }
            float bo = wb[OB4 + o];
            float a, b, c, d;
            unpack2(add2(s0, t0), a, b);
            unpack2(add2(s1, t1), c, d);
            float v0 = a + b + bo;
            float v1 = c + d + bo;
            if (o == 0) { sv0 = v0; sv1 = v1; } else { tv0 = v0; tv1 = v1; }
        }

        ldet0 += sv0; ldet1 += sv1;
        // i = k+1 ; reversed order => z column 31-(k+1) = 30-k
        int is = (k + 1) ^ tx;
        z[r0 * DIMV + (30 - k)]       = fmaf(xs[xb + is],      __expf(sv0), tv0);
        z[(r0 + 1) * DIMV + (30 - k)] = fmaf(xs[xb + 32 + is], __expf(sv1), tv1);

        if (k + 1 < KLV) {
            asm volatile("cp.async.wait_group 0;" ::: "memory");
            __syncthreads();               // next weights visible; old buffer free
            p ^= 1;
        }
    }

    // dim 0: LeafParam p0 (reversed order => column 31)
    float s0v = p0[0], t0v = p0[1];
    float e0 = __expf(s0v);
    int zs = 0 ^ tx;
    z[r0 * DIMV + 31]       = fmaf(xs[xb + zs],      e0, t0v);
    z[(r0 + 1) * DIMV + 31] = fmaf(xs[xb + 32 + zs], e0, t0v);
    ldet0 += s0v; ldet1 += s0v;
    if (logdet) { logdet[r0] = ldet0; logdet[r0 + 1] = ldet1; }
}

extern "C" void kernel_launch(void* const* d_in, const int* in_sizes, int n_in,
                              void* d_out, int out_size)
{
    (void)n_in;
    const float* x  = (const float*)d_in[0];
    const float* p0 = (const float*)d_in[1];
    const float* W1 = (const float*)d_in[2];
    const float* b1 = (const float*)d_in[3];
    const float* W2 = (const float*)d_in[4];
    const float* b2 = (const float*)d_in[5];
    const float* W3 = (const float*)d_in[6];
    const float* b3 = (const float*)d_in[7];
    const float* W4 = (const float*)d_in[8];
    const float* b4 = (const float*)d_in[9];

    const int B = in_sizes[0] / DIMV;
    float* z  = (float*)d_out;
    float* ld = (out_size >= B * (DIMV + 1)) ? z + (size_t)B * DIMV : nullptr;

    prepack_kernel<<<(KLV * BLOBK + 255) / 256, 256>>>(W1, b1, W2, b2, W3, b3, W4, b4);
    // 2 rows per thread, 128 threads => 256 rows per block
    maf_kernel<<<B / (THREADS * 2), THREADS>>>(x, p0, z, ld);
}

// round 12
// speedup vs baseline: 1.2672x; 1.2672x over previous
#include <cuda_runtime.h>
#include <cstdint>

#define THREADS 128
#define DIMV 32
#define NHV 24
#define NP 12      // packed h-pairs per 24
#define KLV 31     // dim-1 stacked layers
#define NGRP 4     // k-split groups
#define BMAX 65536
#define BLOBK 2048 // floats per k in the packed blob

// packed-blob / shared weight-buffer offsets (floats) — W1 transposed to [j][h]
#define OW1 0      // 32*24 = 768
#define OW2 768    // 576
#define OW3 1344   // 576
#define OW4 1920   // 48
#define OB1 1968   // 24
#define OB2 1992   // 24
#define OB3 2016   // 24
#define OB4 2040   // 2
#define WTOT 2042

__device__ float g_blob[KLV * BLOBK];      // pre-transposed weights, 254KB
__device__ float g_ldet[NGRP * BMAX];      // per-group logdet partials, 1MB

// ---- packed f32x2 helpers (sm_100+) ----
__device__ __forceinline__ void ffma2(uint64_t& c, uint64_t a, uint64_t b) {
    asm("fma.rn.f32x2 %0, %1, %2, %0;" : "+l"(c) : "l"(a), "l"(b));
}
__device__ __forceinline__ uint64_t add2(uint64_t a, uint64_t b) {
    uint64_t r; asm("add.rn.f32x2 %0, %1, %2;" : "=l"(r) : "l"(a), "l"(b)); return r;
}
__device__ __forceinline__ uint64_t pack2(float lo, float hi) {
    uint64_t r; asm("mov.b64 %0, {%1, %2};" : "=l"(r) : "f"(lo), "f"(hi)); return r;
}
__device__ __forceinline__ void unpack2(uint64_t v, float& lo, float& hi) {
    asm("mov.b64 {%0, %1}, %2;" : "=f"(lo), "=f"(hi) : "l"(v));
}
__device__ __forceinline__ uint64_t lrelu2(uint64_t v) {
    float lo, hi; unpack2(v, lo, hi);
    lo = fmaxf(lo, 0.2f * lo);
    hi = fmaxf(hi, 0.2f * hi);
    return pack2(lo, hi);
}
__device__ __forceinline__ float lrelu(float v) { return fmaxf(v, 0.2f * v); }

// ---- one-time weight prepack: blob[k][...] with W1 transposed to [j][h] ----
__global__ void prepack_kernel(const float* __restrict__ W1, const float* __restrict__ b1,
                               const float* __restrict__ W2, const float* __restrict__ b2,
                               const float* __restrict__ W3, const float* __restrict__ b3,
                               const float* __restrict__ W4, const float* __restrict__ b4)
{
    int idx = blockIdx.x * blockDim.x + threadIdx.x;
    if (idx >= KLV * BLOBK) return;
    int k = idx >> 11, f = idx & (BLOBK - 1);
    float v = 0.f;
    if (f < 768)       { int j = f / 24, h = f - j * 24; v = W1[k * 768 + h * 32 + j]; }
    else if (f < 1344) v = W2[k * 576 + (f - 768)];
    else if (f < 1920) v = W3[k * 576 + (f - 1344)];
    else if (f < 1968) v = W4[k * 48  + (f - 1920)];
    else if (f < 1992) v = b1[k * 24  + (f - 1968)];
    else if (f < 2016) v = b2[k * 24  + (f - 1992)];
    else if (f < 2040) v = b3[k * 24  + (f - 2016)];
    else if (f < WTOT) v = b4[k * 2   + (f - 2040)];
    g_blob[idx] = v;
}

// ---- final logdet reduce: deterministic 4-way sum ----
__global__ void reduce_ldet_kernel(float* __restrict__ logdet, int B)
{
    int i = blockIdx.x * blockDim.x + threadIdx.x;
    if (i < B)
        logdet[i] = (g_ldet[i] + g_ldet[B + i]) + (g_ldet[2 * B + i] + g_ldet[3 * B + i]);
}

__global__ void __launch_bounds__(THREADS, 3)
maf_kernel(const float* __restrict__ x, const float* __restrict__ p0,
           float* __restrict__ z, int B)
{
    // 256 rows per block (2 per thread), stride-33 padded rows
    __shared__ float xs[THREADS * 2 * 33];      // 33.8 KB
    __shared__ float wbuf[BLOBK];               // 8 KB, cp.async staged per k

    const int tid = threadIdx.x;
    const int g   = blockIdx.y;                 // k-group: handles k = g, g+4, ...
    const size_t r0 = ((size_t)blockIdx.x * THREADS + tid) * 2;
    const int lr0 = 2 * tid, lr1 = 2 * tid + 1;

    // ---- load both x rows into padded shared (thread-private) ----
    {
        const float4* xa = reinterpret_cast<const float4*>(x + r0 * DIMV);
        const float4* xc = reinterpret_cast<const float4*>(x + (r0 + 1) * DIMV);
        #pragma unroll
        for (int q = 0; q < 8; q++) {
            float4 v = xa[q];
            xs[lr0 * 33 + 4 * q + 0] = v.x;  xs[lr0 * 33 + 4 * q + 1] = v.y;
            xs[lr0 * 33 + 4 * q + 2] = v.z;  xs[lr0 * 33 + 4 * q + 3] = v.w;
            float4 w = xc[q];
            xs[lr1 * 33 + 4 * q + 0] = w.x;  xs[lr1 * 33 + 4 * q + 1] = w.y;
            xs[lr1 * 33 + 4 * q + 2] = w.z;  xs[lr1 * 33 + 4 * q + 3] = w.w;
        }
    }

    const uint32_t wsm = (uint32_t)__cvta_generic_to_shared(&wbuf[0]);
    // async weight fetch: 8192 B per k, 4 x 16B per thread
    auto cpw = [&](int k) {
        const char* src = reinterpret_cast<const char*>(g_blob + (size_t)k * BLOBK) + tid * 64;
        uint32_t dst = wsm + tid * 64;
        #pragma unroll
        for (int i = 0; i < 4; i++)
            asm volatile("cp.async.cg.shared.global [%0], [%1], 16;"
                         :: "r"(dst + i * 16), "l"(src + i * 16));
        asm volatile("cp.async.commit_group;");
    };

    cpw(g);
    asm volatile("cp.async.wait_group 0;" ::: "memory");
    __syncthreads();

    float ldet0 = 0.f, ldet1 = 0.f;
    uint64_t A0[NP], A1[NP], B0[NP], B1[NP];

    for (int k = g; k < KLV; k += NGRP) {
        const float* wb = wbuf;

        // ---- layer 1: A[h] = lrelu( sum_{j<=k} W1T[j][h] * x[j] + b1[h] ) ----
        #pragma unroll
        for (int q = 0; q < NP; q++) {
            uint64_t bb = *reinterpret_cast<const uint64_t*>(&wb[OB1 + 2 * q]);
            A0[q] = bb; A1[q] = bb;
        }
        for (int j = 0; j <= k; j++) {
            float x0 = xs[lr0 * 33 + j], x1 = xs[lr1 * 33 + j];
            uint64_t xx0 = pack2(x0, x0), xx1 = pack2(x1, x1);
            const ulonglong2* w = reinterpret_cast<const ulonglong2*>(&wb[OW1 + j * NHV]);
            #pragma unroll
            for (int q = 0; q < 6; q++) {
                ulonglong2 wp = w[q];               // LDS.128 = 2 packed weight pairs
                ffma2(A0[2 * q + 0], wp.x, xx0);
                ffma2(A0[2 * q + 1], wp.y, xx0);
                ffma2(A1[2 * q + 0], wp.x, xx1);
                ffma2(A1[2 * q + 1], wp.y, xx1);
            }
        }
        #pragma unroll
        for (int q = 0; q < NP; q++) { A0[q] = lrelu2(A0[q]); A1[q] = lrelu2(A1[q]); }

        // ---- layer 2: dense 24x24 ----
        #pragma unroll
        for (int Hp = 0; Hp < NP; Hp++) {
            float o0e, o0o, o1e, o1o;
            #pragma unroll
            for (int e = 0; e < 2; e++) {
                int H = 2 * Hp + e;
                const ulonglong2* w = reinterpret_cast<const ulonglong2*>(&wb[OW2 + H * NHV]);
                uint64_t s0 = 0, t0 = 0, s1 = 0, t1 = 0;
                #pragma unroll
                for (int q = 0; q < 6; q++) {
                    ulonglong2 wp = w[q];
                    ffma2(s0, wp.x, A0[2 * q + 0]);
                    ffma2(t0, wp.y, A0[2 * q + 1]);
                    ffma2(s1, wp.x, A1[2 * q + 0]);
                    ffma2(t1, wp.y, A1[2 * q + 1]);
                }
                float bH = wb[OB2 + H];
                float a, b, c, d;
                unpack2(add2(s0, t0), a, b);
                unpack2(add2(s1, t1), c, d);
                float v0 = lrelu(a + b + bH);
                float v1 = lrelu(c + d + bH);
                if (e == 0) { o0e = v0; o1e = v1; } else { o0o = v0; o1o = v1; }
            }
            B0[Hp] = pack2(o0e, o0o);
            B1[Hp] = pack2(o1e, o1o);
        }

        // ---- layer 3: dense 24x24 ----
        #pragma unroll
        for (int Hp = 0; Hp < NP; Hp++) {
            float o0e, o0o, o1e, o1o;
            #pragma unroll
            for (int e = 0; e < 2; e++) {
                int H = 2 * Hp + e;
                const ulonglong2* w = reinterpret_cast<const ulonglong2*>(&wb[OW3 + H * NHV]);
                uint64_t s0 = 0, t0 = 0, s1 = 0, t1 = 0;
                #pragma unroll
                for (int q = 0; q < 6; q++) {
                    ulonglong2 wp = w[q];
                    ffma2(s0, wp.x, B0[2 * q + 0]);
                    ffma2(t0, wp.y, B0[2 * q + 1]);
                    ffma2(s1, wp.x, B1[2 * q + 0]);
                    ffma2(t1, wp.y, B1[2 * q + 1]);
                }
                float bH = wb[OB3 + H];
                float a, b, c, d;
                unpack2(add2(s0, t0), a, b);
                unpack2(add2(s1, t1), c, d);
                float v0 = lrelu(a + b + bH);
                float v1 = lrelu(c + d + bH);
                if (e == 0) { o0e = v0; o1e = v1; } else { o0o = v0; o1o = v1; }
            }
            A0[Hp] = pack2(o0e, o0o);
            A1[Hp] = pack2(o1e, o1o);
        }

        // ---- layer 4: (s, t) per row ----
        float sv0, tv0, sv1, tv1;
        #pragma unroll
        for (int o = 0; o < 2; o++) {
            const ulonglong2* w = reinterpret_cast<const ulonglong2*>(&wb[OW4 + o * NHV]);
            uint64_t s0 = 0, t0 = 0, s1 = 0, t1 = 0;
            #pragma unroll
            for (int q = 0; q < 6; q++) {
                ulonglong2 wp = w[q];
                ffma2(s0, wp.x, A0[2 * q + 0]);
                ffma2(t0, wp.y, A0[2 * q + 1]);
                ffma2(s1, wp.x, A1[2 * q + 0]);
                ffma2(t1, wp.y, A1[2 * q + 1]);
            }
            float bo = wb[OB4 + o];
            float a, b, c, d;
            unpack2(add2(s0, t0), a, b);
            unpack2(add2(s1, t1), c, d);
            float v0 = a + b + bo;
            float v1 = c + d + bo;
            if (o == 0) { sv0 = v0; sv1 = v1; } else { tv0 = v0; tv1 = v1; }
        }

        ldet0 += sv0; ldet1 += sv1;
        // i = k+1 ; reversed order => z column 31-(k+1) = 30-k
        z[r0 * DIMV + (30 - k)]       = fmaf(xs[lr0 * 33 + (k + 1)], __expf(sv0), tv0);
        z[(r0 + 1) * DIMV + (30 - k)] = fmaf(xs[lr1 * 33 + (k + 1)], __expf(sv1), tv1);

        if (k + NGRP < KLV) {
            __syncthreads();                       // everyone done reading wbuf
            cpw(k + NGRP);
            asm volatile("cp.async.wait_group 0;" ::: "memory");
            __syncthreads();                       // refilled wbuf visible
        }
    }

    // dim 0 leaf (p0) handled by group 0: reversed order => column 31
    if (g == 0) {
        float s0v = p0[0], t0v = p0[1];
        float e0 = __expf(s0v);
        z[r0 * DIMV + 31]       = fmaf(xs[lr0 * 33 + 0], e0, t0v);
        z[(r0 + 1) * DIMV + 31] = fmaf(xs[lr1 * 33 + 0], e0, t0v);
        ldet0 += s0v; ldet1 += s0v;
    }
    g_ldet[(size_t)g * B + r0]     = ldet0;
    g_ldet[(size_t)g * B + r0 + 1] = ldet1;
}

extern "C" void kernel_launch(void* const* d_in, const int* in_sizes, int n_in,
                              void* d_out, int out_size)
{
    (void)n_in;
    const float* x  = (const float*)d_in[0];
    const float* p0 = (const float*)d_in[1];
    const float* W1 = (const float*)d_in[2];
    const float* b1 = (const float*)d_in[3];
    const float* W2 = (const float*)d_in[4];
    const float* b2 = (const float*)d_in[5];
    const float* W3 = (const float*)d_in[6];
    const float* b3 = (const float*)d_in[7];
    const float* W4 = (const float*)d_in[8];
    const float* b4 = (const float*)d_in[9];

    const int B = in_sizes[0] / DIMV;
    float* z  = (float*)d_out;
    float* ld = (out_size >= B * (DIMV + 1)) ? z + (size_t)B * DIMV : nullptr;

    prepack_kernel<<<(KLV * BLOBK + 255) / 256, 256>>>(W1, b1, W2, b2, W3, b3, W4, b4);

    // 2 rows/thread, 128 threads => 256 rows per block; k split across 4 groups
    dim3 grid(B / (THREADS * 2), NGRP);
    maf_kernel<<<grid, THREADS>>>(x, p0, z, B);

    if (ld) reduce_ldet_kernel<<<(B + 255) / 256, 256>>>(ld, B);
}